// round 14
// baseline (speedup 1.0000x reference)
#include <cuda_runtime.h>
#include <math.h>

#define HW 65536
#define IMG 256
#define NB 2

// ---------------- scratch (device globals; no allocations allowed) ----------
__device__ float g_y[NB * 96 * HW];        // LN outputs (reused)
__device__ float g_big1[NB * 576 * HW];    // conv1x1 out (hidden_pre / ffn_pre)
__device__ float g_big2[NB * 576 * HW];    // dwconv out  (hidden / ffn hidden)
__device__ float g_attn[NB * 192 * HW];    // attention spatial output
__device__ float g_gate[NB * 255 * HW];    // gelu(x1)*x2

// ---------------- BiasFree LayerNorm over channel dim (96) ------------------
__global__ void ln_kernel(const float* __restrict__ x, const float* __restrict__ w,
                          float* __restrict__ y) {
    long g = (long)blockIdx.x * 256 + threadIdx.x;   // 131072 pixels total
    long b = g >> 16;
    long pix = g & 65535;
    const float* px = x + b * 96L * HW + pix;
    float s = 0.f, s2 = 0.f;
#pragma unroll 8
    for (int c = 0; c < 96; c++) {
        float v = px[(long)c * HW];
        s += v; s2 += v * v;
    }
    float mean = s * (1.f / 96.f);
    float var = s2 * (1.f / 96.f) - mean * mean;
    float sc = 1.f / sqrtf(var + 1e-5f);
    float* py = y + b * 96L * HW + pix;
#pragma unroll 8
    for (int c = 0; c < 96; c++)
        py[(long)c * HW] = px[(long)c * HW] * sc * w[c];
}

// ---------------- conv1x1 as GEMM: out[o,p] = sum_c W[o,c] in[c,p] (+res) ---
// grid: (HW/128, ceil(M/64), B), 256 threads, 4x8 microtile
__global__ void gemm1x1(const float* __restrict__ W, const float* __restrict__ in,
                        const float* res, float* out, int M, int K) {
    __shared__ float As[8][64];
    __shared__ float Bs[8][128];
    int tid = threadIdx.x;
    int nBase = blockIdx.x * 128;
    int mBase = blockIdx.y * 64;
    long bofIn = (long)blockIdx.z * K * HW;
    long bofOut = (long)blockIdx.z * M * HW;
    int tx = tid & 15, ty = tid >> 4;

    float acc[4][8];
#pragma unroll
    for (int i = 0; i < 4; i++)
#pragma unroll
        for (int j = 0; j < 8; j++) acc[i][j] = 0.f;

    int nK = (K + 7) >> 3;
    for (int kb = 0; kb < nK; kb++) {
        int k0 = kb * 8;
        // A: 64 rows x 8 k
#pragma unroll
        for (int r = 0; r < 2; r++) {
            int idx = tid + r * 256;
            int m = idx >> 3, kk = idx & 7;
            int row = mBase + m, kcol = k0 + kk;
            float v = 0.f;
            if (row < M && kcol < K) v = W[(long)row * K + kcol];
            As[kk][m] = v;
        }
        // B: 8 k x 128 p
        {
            int rrow = tid >> 5;
            int c4 = (tid & 31) * 4;
            float4 v = make_float4(0.f, 0.f, 0.f, 0.f);
            if (k0 + rrow < K)
                v = *(const float4*)&in[bofIn + (long)(k0 + rrow) * HW + nBase + c4];
            *(float4*)&Bs[rrow][c4] = v;
        }
        __syncthreads();
#pragma unroll
        for (int kk = 0; kk < 8; kk++) {
            float4 a4 = *(const float4*)(&As[kk][ty * 4]);
            float4 b4a = *(const float4*)(&Bs[kk][tx * 8]);
            float4 b4b = *(const float4*)(&Bs[kk][tx * 8 + 4]);
            float a[4] = {a4.x, a4.y, a4.z, a4.w};
            float bb[8] = {b4a.x, b4a.y, b4a.z, b4a.w, b4b.x, b4b.y, b4b.z, b4b.w};
#pragma unroll
            for (int i = 0; i < 4; i++)
#pragma unroll
                for (int j = 0; j < 8; j++) acc[i][j] = fmaf(a[i], bb[j], acc[i][j]);
        }
        __syncthreads();
    }

#pragma unroll
    for (int i = 0; i < 4; i++) {
        int row = mBase + ty * 4 + i;
        if (row < M) {
            long o = bofOut + (long)row * HW + nBase + tx * 8;
            float4 v0 = make_float4(acc[i][0], acc[i][1], acc[i][2], acc[i][3]);
            float4 v1 = make_float4(acc[i][4], acc[i][5], acc[i][6], acc[i][7]);
            if (res) {
                float4 r0 = *(const float4*)(res + o);
                float4 r1 = *(const float4*)(res + o + 4);
                v0.x += r0.x; v0.y += r0.y; v0.z += r0.z; v0.w += r0.w;
                v1.x += r1.x; v1.y += r1.y; v1.z += r1.z; v1.w += r1.w;
            }
            *(float4*)(out + o) = v0;
            *(float4*)(out + o + 4) = v1;
        }
    }
}

// ---------------- 3x3 depthwise conv (zero pad, cross-correlation) ----------
// grid: (H, C, B), 256 threads = one output row
__global__ void dw3(const float* __restrict__ in, const float* __restrict__ w,
                    float* __restrict__ out, int C) {
    int wx = threadIdx.x;
    int h = blockIdx.x;
    int c = blockIdx.y;
    int b = blockIdx.z;
    long base = ((long)(b * C + c)) * HW;
    float k[9];
#pragma unroll
    for (int i = 0; i < 9; i++) k[i] = w[c * 9 + i];
    float acc = 0.f;
#pragma unroll
    for (int di = 0; di < 3; di++) {
        int hh = h + di - 1;
        if (hh < 0 || hh >= IMG) continue;
        const float* row = in + base + (long)hh * IMG;
#pragma unroll
        for (int dj = 0; dj < 3; dj++) {
            int ww = wx + dj - 1;
            if (ww < 0 || ww >= IMG) continue;
            acc = fmaf(k[di * 3 + dj], row[ww], acc);
        }
    }
    out[base + (long)h * IMG + wx] = acc;
}

// ---------------- exact GELU gate: g = gelu(x1) * x2 ------------------------
__global__ void gelu_mul(const float* __restrict__ t, float* __restrict__ g) {
    long i = (long)blockIdx.x * 256 + threadIdx.x;
    if (i >= (long)NB * 255 * HW) return;
    long b = i / (255L * HW);
    long rest = i - b * 255L * HW;
    const float* tb = t + b * 510L * HW;
    float x1 = tb[rest];
    float x2 = tb[rest + 255L * HW];
    float ge = 0.5f * x1 * (1.f + erff(x1 * 0.70710678118654752f));
    g[i] = ge * x2;
}

// ---------------- FFT attention: one CTA per (b, head, patch) ---------------
// hidden: [B,576,256,256] -> out: [B,192,256,256]
// rfft64 via DFT matmul, 33x33 complex Gram (no conj), row L2 normalize,
// apply to V, irfft64 (numpy convention: Im(X[0]),Im(X[32]) dropped).
#define ATT_SMEM 76044
__global__ void attn_fft(const float* __restrict__ hid, const float* __restrict__ temp,
                         float* __restrict__ osp) {
    extern __shared__ char smemraw[];
    float2* s_tw = (float2*)smemraw;          // 64*33
    float2* s_qf = s_tw + 2112;               // 48*33
    float2* s_kf = s_qf + 1584;
    float2* s_vf = s_kf + 1584;
    float2* s_at = s_vf + 1584;               // 33*33
    float*  s_in = (float*)(s_at + 1089);     // 48*64
    float*  s_inv = s_in + 3072;              // 33

    int tid = threadIdx.x;
    int u = blockIdx.x;
    int b = u >> 12;
    int r = u & 4095;
    int hd = r >> 10;
    int p = r & 1023;
    int ph = p >> 5, pw = p & 31;

    // twiddles: tw[n*33+f] = (cos, sin) of 2*pi*((n*f) mod 64)/64
    for (int i = tid; i < 2112; i += 256) {
        int n = i / 33, f = i - n * 33;
        float th = (float)((n * f) & 63) * 0.0981747704246810387f;
        float sn, cs;
        sincosf(th, &sn, &cs);
        s_tw[i] = make_float2(cs, sn);
    }

    long gbase = ((long)b * 576) * HW + (long)(ph * 8) * IMG + pw * 8;
    float2* dsts[3] = {s_qf, s_kf, s_vf};

    for (int tns = 0; tns < 3; tns++) {
        int cb = tns * 192 + hd * 48;
        __syncthreads();   // protect s_in reuse (+ twiddle fill on first pass)
        for (int i = tid; i < 3072; i += 256) {
            int c = i >> 6, n = i & 63;
            s_in[i] = hid[gbase + (long)(cb + c) * HW + (n >> 3) * IMG + (n & 7)];
        }
        __syncthreads();
        if (tid < 204) {  // rfft: qf[c,f] = sum_n q[c,n] e^{-i 2pi nf/64}
            int fi = tid % 17, ci = tid / 17;
            int f0 = 2 * fi, c0 = 4 * ci;
            bool h1 = (f0 + 1 < 33);
            int f1 = h1 ? f0 + 1 : f0;
            float ar0[4] = {0,0,0,0}, ai0[4] = {0,0,0,0};
            float ar1[4] = {0,0,0,0}, ai1[4] = {0,0,0,0};
#pragma unroll 4
            for (int n = 0; n < 64; n++) {
                float2 t0 = s_tw[n * 33 + f0];
                float2 t1 = s_tw[n * 33 + f1];
#pragma unroll
                for (int i = 0; i < 4; i++) {
                    float q = s_in[(c0 + i) * 64 + n];
                    ar0[i] = fmaf(q, t0.x, ar0[i]); ai0[i] = fmaf(-q, t0.y, ai0[i]);
                    ar1[i] = fmaf(q, t1.x, ar1[i]); ai1[i] = fmaf(-q, t1.y, ai1[i]);
                }
            }
            float2* dst = dsts[tns];
#pragma unroll
            for (int i = 0; i < 4; i++) {
                dst[(c0 + i) * 33 + f0] = make_float2(ar0[i], ai0[i]);
                if (h1) dst[(c0 + i) * 33 + f0 + 1] = make_float2(ar1[i], ai1[i]);
            }
        }
    }
    __syncthreads();

    // attn[f,g] = temp * sum_c qf[c,f]*kf[c,g]  (plain complex product)
    if (tid < 153) {
        int fi = tid % 17, gi = tid / 17;
        int f0 = 2 * fi, g0 = 4 * gi;
        bool h1 = f0 + 1 < 33;
        int f1 = h1 ? f0 + 1 : f0;
        int gg[4];
#pragma unroll
        for (int j = 0; j < 4; j++) gg[j] = (g0 + j > 32) ? 32 : (g0 + j);
        float2 a0[4], a1[4];
#pragma unroll
        for (int j = 0; j < 4; j++) { a0[j] = make_float2(0,0); a1[j] = make_float2(0,0); }
        for (int c = 0; c < 48; c++) {
            float2 q0 = s_qf[c * 33 + f0];
            float2 q1 = s_qf[c * 33 + f1];
#pragma unroll
            for (int j = 0; j < 4; j++) {
                float2 kv = s_kf[c * 33 + gg[j]];
                a0[j].x = fmaf(q0.x, kv.x, fmaf(-q0.y, kv.y, a0[j].x));
                a0[j].y = fmaf(q0.x, kv.y, fmaf(q0.y, kv.x, a0[j].y));
                a1[j].x = fmaf(q1.x, kv.x, fmaf(-q1.y, kv.y, a1[j].x));
                a1[j].y = fmaf(q1.x, kv.y, fmaf(q1.y, kv.x, a1[j].y));
            }
        }
        float tm = temp[hd];
#pragma unroll
        for (int j = 0; j < 4; j++) {
            if (g0 + j < 33) {
                s_at[f0 * 33 + g0 + j] = make_float2(a0[j].x * tm, a0[j].y * tm);
                if (h1) s_at[(f0 + 1) * 33 + g0 + j] = make_float2(a1[j].x * tm, a1[j].y * tm);
            }
        }
    }
    __syncthreads();

    // row norms (per f, over g)
    if (tid < 33) {
        float s = 0.f;
        for (int gg = 0; gg < 33; gg++) {
            float2 a = s_at[tid * 33 + gg];
            s += a.x * a.x + a.y * a.y;
        }
        s_inv[tid] = 1.f / sqrtf(s);
    }
    __syncthreads();

    // out[c,f] = inv[f] * sum_g attn[f,g]*vf[c,g]   (stored into s_qf)
    if (tid < 204) {
        int fi = tid % 17, ci = tid / 17;
        int f0 = 2 * fi, c0 = 4 * ci;
        bool h1 = f0 + 1 < 33;
        int f1 = h1 ? f0 + 1 : f0;
        float2 o0[4], o1[4];
#pragma unroll
        for (int i = 0; i < 4; i++) { o0[i] = make_float2(0,0); o1[i] = make_float2(0,0); }
        for (int gg = 0; gg < 33; gg++) {
            float2 A0 = s_at[f0 * 33 + gg];
            float2 A1 = s_at[f1 * 33 + gg];
#pragma unroll
            for (int i = 0; i < 4; i++) {
                float2 v = s_vf[(c0 + i) * 33 + gg];
                o0[i].x = fmaf(A0.x, v.x, fmaf(-A0.y, v.y, o0[i].x));
                o0[i].y = fmaf(A0.x, v.y, fmaf(A0.y, v.x, o0[i].y));
                o1[i].x = fmaf(A1.x, v.x, fmaf(-A1.y, v.y, o1[i].x));
                o1[i].y = fmaf(A1.x, v.y, fmaf(A1.y, v.x, o1[i].y));
            }
        }
        float v0 = s_inv[f0], v1 = s_inv[f1];
#pragma unroll
        for (int i = 0; i < 4; i++) {
            s_qf[(c0 + i) * 33 + f0] = make_float2(o0[i].x * v0, o0[i].y * v0);
            if (h1) s_qf[(c0 + i) * 33 + f0 + 1] = make_float2(o1[i].x * v1, o1[i].y * v1);
        }
    }
    __syncthreads();

    // irfft (n=64): x[n] = (ReX0 + (-1)^n ReX32 + 2*sum_{k=1..31}(ReX cos - ImX sin))/64
    long obase = ((long)b * 192 + hd * 48) * HW + (long)(ph * 8) * IMG + pw * 8;
    for (int rr = 0; rr < 2; rr++) {
        int task = tid + rr * 256;
        if (task < 384) {
            int ni = task & 31, ci = task >> 5;
            int n0 = 2 * ni, c0 = 4 * ci;
            float b0[4], b1[4], s0[4] = {0,0,0,0}, s1[4] = {0,0,0,0};
#pragma unroll
            for (int i = 0; i < 4; i++) {
                float2 X0 = s_qf[(c0 + i) * 33];
                float2 XN = s_qf[(c0 + i) * 33 + 32];
                b0[i] = X0.x + XN.x;   // n even
                b1[i] = X0.x - XN.x;   // n odd
            }
            for (int k = 1; k < 32; k++) {
                float2 t0 = s_tw[n0 * 33 + k];
                float2 t1 = s_tw[(n0 + 1) * 33 + k];
#pragma unroll
                for (int i = 0; i < 4; i++) {
                    float2 X = s_qf[(c0 + i) * 33 + k];
                    s0[i] = fmaf(X.x, t0.x, fmaf(-X.y, t0.y, s0[i]));
                    s1[i] = fmaf(X.x, t1.x, fmaf(-X.y, t1.y, s1[i]));
                }
            }
            int p1 = n0 >> 3, p2 = n0 & 7;
#pragma unroll
            for (int i = 0; i < 4; i++) {
                float r0 = (b0[i] + 2.f * s0[i]) * (1.f / 64.f);
                float r1 = (b1[i] + 2.f * s1[i]) * (1.f / 64.f);
                float2* dst = (float2*)&osp[obase + (long)(c0 + i) * HW + p1 * IMG + p2];
                *dst = make_float2(r0, r1);
            }
        }
    }
}

// ---------------- launch ----------------------------------------------------
extern "C" void kernel_launch(void* const* d_in, const int* in_sizes, int n_in,
                              void* d_out, int out_size) {
    const float* x      = (const float*)d_in[0];
    const float* w_hid  = (const float*)d_in[1];   // (576,96)
    const float* w_hdw  = (const float*)d_in[2];   // (576,1,3,3)
    const float* w_proj = (const float*)d_in[3];   // (96,192)
    const float* temp   = (const float*)d_in[4];   // (4,1,1,1)
    const float* n1     = (const float*)d_in[5];
    const float* n2     = (const float*)d_in[6];
    const float* w_fin  = (const float*)d_in[7];   // (510,96)
    const float* w_fdw  = (const float*)d_in[8];   // (510,1,3,3)
    const float* w_fout = (const float*)d_in[9];   // (96,255)
    float* out = (float*)d_out;

    float *y, *b1, *b2, *at, *gg;
    cudaGetSymbolAddress((void**)&y, g_y);
    cudaGetSymbolAddress((void**)&b1, g_big1);
    cudaGetSymbolAddress((void**)&b2, g_big2);
    cudaGetSymbolAddress((void**)&at, g_attn);
    cudaGetSymbolAddress((void**)&gg, g_gate);

    cudaFuncSetAttribute(attn_fft, cudaFuncAttributeMaxDynamicSharedMemorySize, ATT_SMEM);

    // --- attention branch ---
    ln_kernel<<<512, 256>>>(x, n1, y);
    gemm1x1<<<dim3(512, 9, 2), 256>>>(w_hid, y, nullptr, b1, 576, 96);
    dw3<<<dim3(256, 576, 2), 256>>>(b1, w_hdw, b2, 576);
    attn_fft<<<8192, 256, ATT_SMEM>>>(b2, temp, at);
    gemm1x1<<<dim3(512, 2, 2), 256>>>(w_proj, at, x, out, 96, 192);   // out = x1

    // --- FFN branch ---
    ln_kernel<<<512, 256>>>(out, n2, y);
    gemm1x1<<<dim3(512, 8, 2), 256>>>(w_fin, y, nullptr, b1, 510, 96);
    dw3<<<dim3(256, 510, 2), 256>>>(b1, w_fdw, b2, 510);
    gelu_mul<<<130560, 256>>>(b2, gg);
    gemm1x1<<<dim3(512, 2, 2), 256>>>(w_fout, gg, out, out, 96, 255); // final
}

// round 16
// speedup vs baseline: 1.7701x; 1.7701x over previous
#include <cuda_runtime.h>
#include <math.h>

#define HW 65536
#define IMG 256
#define NB 2

// ---------------- scratch (device globals; no allocations allowed) ----------
__device__ float g_y[NB * 96 * HW];
__device__ float g_big1[NB * 576 * HW];
__device__ float g_big2[NB * 576 * HW];
__device__ float g_attn[NB * 192 * HW];
__device__ float g_gate[NB * 255 * HW];

// ---------------- BiasFree LayerNorm over channel dim (96) ------------------
__global__ void ln_kernel(const float* __restrict__ x, const float* __restrict__ w,
                          float* __restrict__ y) {
    long g = (long)blockIdx.x * 256 + threadIdx.x;
    long b = g >> 16;
    long pix = g & 65535;
    const float* px = x + b * 96L * HW + pix;
    float s = 0.f, s2 = 0.f;
#pragma unroll 8
    for (int c = 0; c < 96; c++) {
        float v = px[(long)c * HW];
        s += v; s2 += v * v;
    }
    float mean = s * (1.f / 96.f);
    float var = s2 * (1.f / 96.f) - mean * mean;
    float sc = 1.f / sqrtf(var + 1e-5f);
    float* py = y + b * 96L * HW + pix;
#pragma unroll 8
    for (int c = 0; c < 96; c++)
        py[(long)c * HW] = px[(long)c * HW] * sc * w[c];
}

// ---------------- conv1x1 GEMM: out[o,p] = sum_c W[o,c] in[c,p] (+res) ------
// 64x256 tile, 8x8 microtile, double-buffered smem. grid (256, ceil(M/64), B)
#define BM 64
#define BN 256
#define BK 8
__global__ void __launch_bounds__(256, 2)
gemm1x1(const float* __restrict__ W, const float* __restrict__ in,
        const float* __restrict__ res, float* __restrict__ out, int M, int K) {
    __shared__ float As[2][BK][BM];
    __shared__ float Bs[2][BK][BN];
    int tid = threadIdx.x;
    int tx = tid & 31;           // n-group
    int ty = tid >> 5;           // m-group (warp)
    int nBase = blockIdx.x * BN;
    int mBase = blockIdx.y * BM;
    long bofIn = (long)blockIdx.z * K * HW;
    long bofOut = (long)blockIdx.z * M * HW;

    int brow = tid >> 5, bcol = tx * 8;
    int am = tid >> 2, ak = (tid & 3) * 2;
    int arow = mBase + am;

    float acc[8][8];
#pragma unroll
    for (int i = 0; i < 8; i++)
#pragma unroll
        for (int j = 0; j < 8; j++) acc[i][j] = 0.f;

    // prologue: tile 0
    {
        float4 b0 = make_float4(0,0,0,0), b1 = make_float4(0,0,0,0);
        if (brow < K) {
            const float* src = &in[bofIn + (long)brow * HW + nBase + bcol];
            b0 = *(const float4*)src; b1 = *(const float4*)(src + 4);
        }
        *(float4*)&Bs[0][brow][bcol] = b0;
        *(float4*)&Bs[0][brow][bcol + 4] = b1;
        As[0][ak][am]     = (arow < M && ak < K)     ? W[(long)arow * K + ak]     : 0.f;
        As[0][ak + 1][am] = (arow < M && ak + 1 < K) ? W[(long)arow * K + ak + 1] : 0.f;
    }
    __syncthreads();

    int nK = (K + BK - 1) / BK;
    for (int kb = 0; kb < nK; kb++) {
        int cur = kb & 1;
        float4 nb0, nb1; float na0 = 0.f, na1 = 0.f;
        bool hasNext = (kb + 1 < nK);
        if (hasNext) {
            int k0 = (kb + 1) * BK;
            nb0 = make_float4(0,0,0,0); nb1 = make_float4(0,0,0,0);
            if (k0 + brow < K) {
                const float* src = &in[bofIn + (long)(k0 + brow) * HW + nBase + bcol];
                nb0 = *(const float4*)src; nb1 = *(const float4*)(src + 4);
            }
            na0 = (arow < M && k0 + ak < K)     ? W[(long)arow * K + k0 + ak]     : 0.f;
            na1 = (arow < M && k0 + ak + 1 < K) ? W[(long)arow * K + k0 + ak + 1] : 0.f;
        }
#pragma unroll
        for (int kk = 0; kk < BK; kk++) {
            float4 a0 = *(const float4*)&As[cur][kk][ty * 8];
            float4 a1 = *(const float4*)&As[cur][kk][ty * 8 + 4];
            float4 c0 = *(const float4*)&Bs[cur][kk][tx * 8];
            float4 c1 = *(const float4*)&Bs[cur][kk][tx * 8 + 4];
            float a[8] = {a0.x, a0.y, a0.z, a0.w, a1.x, a1.y, a1.z, a1.w};
            float bb[8] = {c0.x, c0.y, c0.z, c0.w, c1.x, c1.y, c1.z, c1.w};
#pragma unroll
            for (int i = 0; i < 8; i++)
#pragma unroll
                for (int j = 0; j < 8; j++) acc[i][j] = fmaf(a[i], bb[j], acc[i][j]);
        }
        if (hasNext) {
            int nxt = cur ^ 1;
            *(float4*)&Bs[nxt][brow][bcol] = nb0;
            *(float4*)&Bs[nxt][brow][bcol + 4] = nb1;
            As[nxt][ak][am] = na0;
            As[nxt][ak + 1][am] = na1;
        }
        __syncthreads();
    }

#pragma unroll
    for (int i = 0; i < 8; i++) {
        int row = mBase + ty * 8 + i;
        if (row < M) {
            long o = bofOut + (long)row * HW + nBase + tx * 8;
            float4 v0 = make_float4(acc[i][0], acc[i][1], acc[i][2], acc[i][3]);
            float4 v1 = make_float4(acc[i][4], acc[i][5], acc[i][6], acc[i][7]);
            if (res) {
                float4 r0 = *(const float4*)(res + o);
                float4 r1 = *(const float4*)(res + o + 4);
                v0.x += r0.x; v0.y += r0.y; v0.z += r0.z; v0.w += r0.w;
                v1.x += r1.x; v1.y += r1.y; v1.z += r1.z; v1.w += r1.w;
            }
            *(float4*)(out + o) = v0;
            *(float4*)(out + o + 4) = v1;
        }
    }
}

// ---------------- 3x3 depthwise conv, smem-tiled 4 rows ---------------------
// grid: (64, C, B), 256 threads
__global__ void dw3(const float* __restrict__ in, const float* __restrict__ w,
                    float* __restrict__ out, int C) {
    __shared__ float s[6][258];
    int wx = threadIdx.x;
    int h0 = blockIdx.x * 4;
    int c = blockIdx.y;
    int b = blockIdx.z;
    long base = ((long)(b * C + c)) * HW;
    float k[9];
#pragma unroll
    for (int i = 0; i < 9; i++) k[i] = w[c * 9 + i];
#pragma unroll
    for (int r = 0; r < 6; r++) {
        int hh = h0 - 1 + r;
        float v = (hh >= 0 && hh < IMG) ? in[base + (long)hh * IMG + wx] : 0.f;
        s[r][wx + 1] = v;
        if (wx == 0) { s[r][0] = 0.f; s[r][257] = 0.f; }
    }
    __syncthreads();
#pragma unroll
    for (int r = 0; r < 4; r++) {
        float acc = 0.f;
#pragma unroll
        for (int di = 0; di < 3; di++)
#pragma unroll
            for (int dj = 0; dj < 3; dj++)
                acc = fmaf(k[di * 3 + dj], s[r + di][wx + dj], acc);
        out[base + (long)(h0 + r) * IMG + wx] = acc;
    }
}

// ---------------- exact GELU gate -------------------------------------------
__global__ void gelu_mul(const float* __restrict__ t, float* __restrict__ g) {
    long i = (long)blockIdx.x * 256 + threadIdx.x;
    if (i >= (long)NB * 255 * HW) return;
    long b = i / (255L * HW);
    long rest = i - b * 255L * HW;
    const float* tb = t + b * 510L * HW;
    float x1 = tb[rest];
    float x2 = tb[rest + 255L * HW];
    float ge = 0.5f * x1 * (1.f + erff(x1 * 0.70710678118654752f));
    g[i] = ge * x2;
}

// ---------------- FFT attention (radix-2, register twiddles) ----------------
// One CTA per (b, head, patch). 8 warps: warp = 6 channels, lane = frequency.
// smem: qf/kf/vf [48][33] float2 + s_in [64][50] (aliased by s_at [33][33]+inv)
// stride 50 (even) keeps every float2 access 8-byte aligned.
#define ATT_SMEM (3 * 1584 * 8 + 3200 * 4)
__global__ void __launch_bounds__(256, 4)
attn_fft(const float* __restrict__ hid, const float* __restrict__ temp,
         float* __restrict__ osp) {
    extern __shared__ float sm[];
    float2* s_qf = (float2*)sm;            // 48*33
    float2* s_kf = s_qf + 1584;
    float2* s_vf = s_kf + 1584;
    float*  s_in = (float*)(s_vf + 1584);  // 64*50 floats (padded, even stride)
    float2* s_at = (float2*)s_in;          // alias: 33*33 float2 (layout [g][f])
    float*  s_inv = (float*)(s_at + 1089); // 33 floats

    int tid = threadIdx.x;
    int lane = tid & 31;
    int wrp = tid >> 5;
    int cbase = wrp * 6;

    int u = blockIdx.x;
    int b = u >> 12;
    int r = u & 4095;
    int hd = r >> 10;
    int p = r & 1023;
    int ph = p >> 5, pw = p & 31;

    long gbase = ((long)b * 576) * HW + (long)(ph * 8) * IMG + pw * 8;
    float tm = temp[hd];

    float sn32, cs32; sincosf((float)lane * 0.19634954084936207f, &sn32, &cs32);
    float sn64, cs64; sincosf((float)lane * 0.09817477042468103f, &sn64, &cs64);

    float2* dsts[3] = {s_qf, s_kf, s_vf};

    // ---- rfft64 of q,k,v via radix-2 + twiddle recurrence ----
    for (int tns = 0; tns < 3; tns++) {
        int cb = tns * 192 + hd * 48;
        __syncthreads();
        for (int i = tid; i < 3072; i += 256) {
            int c = i >> 6, n = i & 63;
            s_in[n * 50 + c] = hid[gbase + (long)(cb + c) * HW + (n >> 3) * IMG + (n & 7)];
        }
        __syncthreads();

        float er[6], ei[6], orr[6], oi[6];
#pragma unroll
        for (int j = 0; j < 6; j++) { er[j] = ei[j] = orr[j] = oi[j] = 0.f; }
        float twx = 1.f, twy = 0.f;   // e^{-i 2pi m lane/32}
#pragma unroll 4
        for (int m = 0; m < 32; m++) {
            const float* pe = &s_in[(2 * m) * 50 + cbase];
            const float* po = &s_in[(2 * m + 1) * 50 + cbase];
            float2 e0 = *(const float2*)pe, e1 = *(const float2*)(pe + 2), e2 = *(const float2*)(pe + 4);
            float2 o0 = *(const float2*)po, o1 = *(const float2*)(po + 2), o2 = *(const float2*)(po + 4);
            float qe[6] = {e0.x, e0.y, e1.x, e1.y, e2.x, e2.y};
            float qo[6] = {o0.x, o0.y, o1.x, o1.y, o2.x, o2.y};
#pragma unroll
            for (int j = 0; j < 6; j++) {
                er[j]  = fmaf(qe[j], twx, er[j]);
                ei[j]  = fmaf(qe[j], twy, ei[j]);
                orr[j] = fmaf(qo[j], twx, orr[j]);
                oi[j]  = fmaf(qo[j], twy, oi[j]);
            }
            float ntx = fmaf(twx, cs32, twy * sn32);
            twy = fmaf(twy, cs32, -twx * sn32);
            twx = ntx;
        }
        // X[lane] = E + e^{-i 2pi lane/64} * O ; X[32] = E0 - O0 (at lane 0)
        float2* dst = dsts[tns];
#pragma unroll
        for (int j = 0; j < 6; j++) {
            float orx = fmaf(orr[j], cs64, oi[j] * sn64);
            float ory = fmaf(oi[j], cs64, -orr[j] * sn64);
            dst[(cbase + j) * 33 + lane] = make_float2(er[j] + orx, ei[j] + ory);
        }
        if (lane == 0) {
#pragma unroll
            for (int j = 0; j < 6; j++)
                dst[(cbase + j) * 33 + 32] = make_float2(er[j] - orr[j], 0.f);
        }
    }
    __syncthreads();

    // ---- Gram: at[g][f] = tm * sum_c qf[c,f]*kf[c,g]  (no conj) ----
    {
        float2 acc[4];
#pragma unroll
        for (int j = 0; j < 4; j++) acc[j] = make_float2(0.f, 0.f);
        int g0 = wrp * 4;
        for (int c = 0; c < 48; c++) {
            float2 q = s_qf[c * 33 + lane];
#pragma unroll
            for (int j = 0; j < 4; j++) {
                float2 k = s_kf[c * 33 + g0 + j];
                acc[j].x = fmaf(q.x, k.x, fmaf(-q.y, k.y, acc[j].x));
                acc[j].y = fmaf(q.x, k.y, fmaf(q.y, k.x, acc[j].y));
            }
        }
#pragma unroll
        for (int j = 0; j < 4; j++)
            s_at[(g0 + j) * 33 + lane] = make_float2(acc[j].x * tm, acc[j].y * tm);
        // leftovers: (f=32, g=0..32) and (f=0..31, g=32)
        if (tid < 65) {
            int f, g;
            if (tid < 33) { f = 32; g = tid; } else { f = tid - 33; g = 32; }
            float2 a = make_float2(0.f, 0.f);
            for (int c = 0; c < 48; c++) {
                float2 q = s_qf[c * 33 + f];
                float2 k = s_kf[c * 33 + g];
                a.x = fmaf(q.x, k.x, fmaf(-q.y, k.y, a.x));
                a.y = fmaf(q.x, k.y, fmaf(q.y, k.x, a.y));
            }
            s_at[g * 33 + f] = make_float2(a.x * tm, a.y * tm);
        }
    }
    __syncthreads();

    // ---- row L2 norms over g ----
    if (tid < 33) {
        float s = 0.f;
        for (int g = 0; g < 33; g++) {
            float2 a = s_at[g * 33 + tid];
            s = fmaf(a.x, a.x, fmaf(a.y, a.y, s));
        }
        s_inv[tid] = 1.f / sqrtf(s);
    }
    __syncthreads();

    // ---- apply: out[c,f] = inv[f] * sum_g at[f,g]*vf[c,g]  -> s_qf ----
    {
        float2 o[6];
#pragma unroll
        for (int j = 0; j < 6; j++) o[j] = make_float2(0.f, 0.f);
        for (int g = 0; g < 33; g++) {
            float2 a = s_at[g * 33 + lane];
#pragma unroll
            for (int j = 0; j < 6; j++) {
                float2 v = s_vf[(cbase + j) * 33 + g];
                o[j].x = fmaf(a.x, v.x, fmaf(-a.y, v.y, o[j].x));
                o[j].y = fmaf(a.x, v.y, fmaf(a.y, v.x, o[j].y));
            }
        }
        float iv = s_inv[lane];
#pragma unroll
        for (int j = 0; j < 6; j++)
            s_qf[(cbase + j) * 33 + lane] = make_float2(o[j].x * iv, o[j].y * iv);
        if (tid < 48) {   // f = 32 tail, one channel per thread
            int c = tid;
            float2 a32 = make_float2(0.f, 0.f);
            for (int g = 0; g < 33; g++) {
                float2 a = s_at[g * 33 + 32];
                float2 v = s_vf[c * 33 + g];
                a32.x = fmaf(a.x, v.x, fmaf(-a.y, v.y, a32.x));
                a32.y = fmaf(a.x, v.y, fmaf(a.y, v.x, a32.y));
            }
            float iv32 = s_inv[32];
            s_qf[c * 33 + 32] = make_float2(a32.x * iv32, a32.y * iv32);
        }
    }
    __syncthreads();

    // ---- irfft64: lane -> n=lane & n=lane+32 (terms differ by (-1)^k) ----
    {
        float sA[6], sB[6];
#pragma unroll
        for (int j = 0; j < 6; j++) { sA[j] = sB[j] = 0.f; }
        float tx2 = cs64, ty2 = sn64;   // e^{+i 2pi lane k/64}, k starts at 1
        float sgn = -1.f;
        for (int k = 1; k <= 31; k++) {
#pragma unroll
            for (int j = 0; j < 6; j++) {
                float2 X = s_qf[(cbase + j) * 33 + k];
                float t = X.x * tx2;
                t = fmaf(-X.y, ty2, t);
                sA[j] += t;
                sB[j] = fmaf(sgn, t, sB[j]);
            }
            float ntx = fmaf(tx2, cs64, -ty2 * sn64);
            ty2 = fmaf(ty2, cs64, tx2 * sn64);
            tx2 = ntx;
            sgn = -sgn;
        }
        long obase = ((long)b * 192 + hd * 48) * HW + (long)(ph * 8) * IMG + pw * 8;
        int nA = lane, nB = lane + 32;
#pragma unroll
        for (int j = 0; j < 6; j++) {
            float2 X0 = s_qf[(cbase + j) * 33];
            float X32 = s_qf[(cbase + j) * 33 + 32].x;
            float base0 = X0.x + ((lane & 1) ? -X32 : X32);
            float rA = (base0 + 2.f * sA[j]) * (1.f / 64.f);
            float rB = (base0 + 2.f * sB[j]) * (1.f / 64.f);
            osp[obase + (long)(cbase + j) * HW + (nA >> 3) * IMG + (nA & 7)] = rA;
            osp[obase + (long)(cbase + j) * HW + (nB >> 3) * IMG + (nB & 7)] = rB;
        }
    }
}

// ---------------- launch ----------------------------------------------------
extern "C" void kernel_launch(void* const* d_in, const int* in_sizes, int n_in,
                              void* d_out, int out_size) {
    const float* x      = (const float*)d_in[0];
    const float* w_hid  = (const float*)d_in[1];
    const float* w_hdw  = (const float*)d_in[2];
    const float* w_proj = (const float*)d_in[3];
    const float* temp   = (const float*)d_in[4];
    const float* n1     = (const float*)d_in[5];
    const float* n2     = (const float*)d_in[6];
    const float* w_fin  = (const float*)d_in[7];
    const float* w_fdw  = (const float*)d_in[8];
    const float* w_fout = (const float*)d_in[9];
    float* out = (float*)d_out;

    float *y, *b1, *b2, *at, *gg;
    cudaGetSymbolAddress((void**)&y, g_y);
    cudaGetSymbolAddress((void**)&b1, g_big1);
    cudaGetSymbolAddress((void**)&b2, g_big2);
    cudaGetSymbolAddress((void**)&at, g_attn);
    cudaGetSymbolAddress((void**)&gg, g_gate);

    cudaFuncSetAttribute(attn_fft, cudaFuncAttributeMaxDynamicSharedMemorySize, ATT_SMEM);

    // --- attention branch ---
    ln_kernel<<<512, 256>>>(x, n1, y);
    gemm1x1<<<dim3(256, 9, 2), 256>>>(w_hid, y, nullptr, b1, 576, 96);
    dw3<<<dim3(64, 576, 2), 256>>>(b1, w_hdw, b2, 576);
    attn_fft<<<8192, 256, ATT_SMEM>>>(b2, temp, at);
    gemm1x1<<<dim3(256, 2, 2), 256>>>(w_proj, at, x, out, 96, 192);

    // --- FFN branch ---
    ln_kernel<<<512, 256>>>(out, n2, y);
    gemm1x1<<<dim3(256, 8, 2), 256>>>(w_fin, y, nullptr, b1, 510, 96);
    dw3<<<dim3(64, 510, 2), 256>>>(b1, w_fdw, b2, 510);
    gelu_mul<<<130560, 256>>>(b2, gg);
    gemm1x1<<<dim3(256, 2, 2), 256>>>(w_fout, gg, out, out, 96, 255);
}